// round 14
// baseline (speedup 1.0000x reference)
#include <cuda_runtime.h>
#include <cuda_bf16.h>

// Per-species linear (X[n,64] . W[species[n],64,1]) + segment_sum over sorted
// structural_indices -> out[n_structures].
// R13: dynamic work-stealing. Persistent single-wave grid (740 CTAs = 148 SMs
// x 5); each warp grabs 256-atom chunks from a global atomic counter until the
// pool is empty -> zero end-of-kernel tail (the residual ncu shows vs static
// schedules). Counter is monotone, so each warp's chunks are increasing in
// index and the sorted-run aggregation (cur_key persists across grabs)
// remains valid. 8-atom batches, int32 indexing, __ldcs streaming (from R10).

#define WARPS_PER_BLOCK 8
#define THREADS_PER_BLOCK (WARPS_PER_BLOCK * 32)
#define CTAS_PER_SM 5
#define NUM_SMS 148
#define N_SPECIES 8
#define D_VEC4 16          // 64 floats / 4
#define CHUNK_ATOMS 256    // multiple of 8 (keeps int4 key/species alignment)

__device__ int g_chunk_counter;

__global__ __launch_bounds__(THREADS_PER_BLOCK, CTAS_PER_SM)
void atomistic_kernel(const float4* __restrict__ X4,
                      const float*  __restrict__ W,
                      const int*    __restrict__ species,
                      const int*    __restrict__ struct_idx,
                      float*        __restrict__ out,
                      int n_atoms)
{
    __shared__ float4 Wsh[N_SPECIES * D_VEC4];
    for (int i = threadIdx.x; i < N_SPECIES * D_VEC4; i += blockDim.x)
        Wsh[i] = reinterpret_cast<const float4*>(W)[i];
    __syncthreads();

    const int lane = threadIdx.x & 31;
    const int half = lane >> 4;                  // which 4-atom group of the batch
    const int sub  = lane & 15;                  // float4 column within the row
    const unsigned halfmask = 0xFFFFu << (half * 16);

    const int n_chunks = (n_atoms + CHUNK_ATOMS - 1) / CHUNK_ATOMS;

    int   cur_key = -1;
    float acc0 = 0.0f, acc1 = 0.0f;

    // Flush the current segment for this half-warp (call half-converged).
    auto flush = [&]() {
        float t = acc0 + acc1;
        t += __shfl_xor_sync(halfmask, t, 8);
        t += __shfl_xor_sync(halfmask, t, 4);
        t += __shfl_xor_sync(halfmask, t, 2);
        t += __shfl_xor_sync(halfmask, t, 1);
        if (sub == 0 && cur_key >= 0)
            atomicAdd(out + cur_key, t);
    };
    // Process one atom with boundary check (slow path / tail).
    auto proc1 = [&](int k, int s, float4 x) {
        if (k != cur_key) {
            flush();
            cur_key = k; acc0 = 0.0f; acc1 = 0.0f;
        }
        const float4 w = Wsh[s * D_VEC4 + sub];
        acc0 = fmaf(x.x, w.x, acc0);
        acc1 = fmaf(x.y, w.y, acc1);
        acc0 = fmaf(x.z, w.z, acc0);
        acc1 = fmaf(x.w, w.w, acc1);
    };
    // One fully-loaded atom on the fast path.
    auto fma4 = [&](int s, const float4& x) {
        const float4 w = Wsh[s * D_VEC4 + sub];
        acc0 = fmaf(x.x, w.x, acc0);
        acc1 = fmaf(x.y, w.y, acc1);
        acc0 = fmaf(x.z, w.z, acc0);
        acc1 = fmaf(x.w, w.w, acc1);
    };

    // Work-stealing loop: grab monotonically increasing 256-atom chunks.
    for (;;) {
        int chunk;
        if (lane == 0)
            chunk = atomicAdd(&g_chunk_counter, 1);
        chunk = __shfl_sync(0xFFFFFFFFu, chunk, 0);
        if (chunk >= n_chunks) break;

        const int start = chunk * CHUNK_ATOMS;
        int end = start + CHUNK_ATOMS;
        if (end > n_atoms) end = n_atoms;
        const int nbatch = (end - start) >> 3;   // batches of 8 atoms

        // Hot-loop pointers (this half's first atom is start + half*4).
        const int a0 = start + half * 4;
        const float4* xp = X4 + (size_t)a0 * D_VEC4 + sub;
        const int*    kp = struct_idx + a0;
        const int*    sp = species + a0;

        for (int b = 0; b < nbatch; ++b) {
            // Front-batched loads: 4 independent streaming float4s + keys.
            const float4 x0 = __ldcs(xp);
            const float4 x1 = __ldcs(xp + 1 * D_VEC4);
            const float4 x2 = __ldcs(xp + 2 * D_VEC4);
            const float4 x3 = __ldcs(xp + 3 * D_VEC4);
            const int4 kv = *reinterpret_cast<const int4*>(kp);
            const int4 sv = *reinterpret_cast<const int4*>(sp);
            xp += 8 * D_VEC4;   // 8 atoms forward (both halves)
            kp += 8;
            sp += 8;

            if (kv.x == cur_key && kv.w == cur_key) {
                // Sorted keys + first==last==cur -> all 4 in current segment.
                fma4(sv.x, x0); fma4(sv.y, x1); fma4(sv.z, x2); fma4(sv.w, x3);
            } else {
                proc1(kv.x, sv.x, x0);
                proc1(kv.y, sv.y, x1);
                proc1(kv.z, sv.z, x2);
                proc1(kv.w, sv.w, x3);
            }
        }

        // Tail (< 8 atoms, only the last chunk): 2 atoms per step, halves
        // interleave; keys stay monotone per half.
        for (int a = start + nbatch * 8 + half; a < end; a += 2) {
            const int k = struct_idx[a];
            const int s = species[a];
            const float4 x = __ldcs(&X4[(size_t)a * D_VEC4 + sub]);
            proc1(k, s, x);
        }
    }

    // Final flush (all lanes converged here).
    flush();
}

extern "C" void kernel_launch(void* const* d_in, const int* in_sizes, int n_in,
                              void* d_out, int out_size)
{
    // Input order: X, W, central_species, structural_indices, n_structures
    const float* X  = (const float*)d_in[0];
    const float* W  = (const float*)d_in[1];
    const int*   sp = (const int*)  d_in[2];
    const int*   si = (const int*)  d_in[3];
    float* out = (float*)d_out;

    const int n_atoms = in_sizes[2];

    // Reset work-stealing counter + zero output (both graph-capturable).
    void* ctr_ptr = nullptr;
    cudaGetSymbolAddress(&ctr_ptr, g_chunk_counter);
    cudaMemsetAsync(ctr_ptr, 0, sizeof(int), 0);
    cudaMemsetAsync(d_out, 0, (size_t)out_size * sizeof(float), 0);

    // Persistent single wave: 148 SMs x 5 CTAs/SM, all resident; warps pull
    // 256-atom chunks until the pool drains.
    const int blocks = NUM_SMS * CTAS_PER_SM;   // 740

    atomistic_kernel<<<blocks, THREADS_PER_BLOCK>>>(
        (const float4*)X, W, sp, si, out, n_atoms);
}